// round 2
// baseline (speedup 1.0000x reference)
#include <cuda_runtime.h>

// Problem constants
#define SSP 32768           // H*W*D = 32*32*32
#define NB 4
#define NCH 128             // input channels C
#define NO 128              // output channels O
#define NCTA_GEMM 1024      // B * (SSP/128)

// Scratch (no allocations allowed): 64MB x_j, transposed W, BN partials, BN affine
__device__ float g_xj[NB * NCH * SSP];
__device__ float g_wt[256 * 128];
__device__ float g_part[2 * NCTA_GEMM * 128];
__device__ float g_scale[128];
__device__ float g_shift[128];

// ---------------------------------------------------------------------------
// Kernel 1: x_j. One CTA per (b,c) slice of 32x32x32 floats held in SMEM.
// x_j = max(0, x - min over same-parity-excluding-self along each axis).
// Exclusive min from (min1, argmin, min2) per line/parity.
// SMEM: 32768 slice + 3 axes * (min1,min2,idx)[2048] = 51200 floats = 200KB.
// ---------------------------------------------------------------------------
__global__ __launch_bounds__(512) void xj_kernel(const float* __restrict__ x) {
    extern __shared__ float sm[];
    float* s  = sm;            // [32][32][32]  (h,w,d)
    float* st = sm + 32768;    // stats: [axis][3][2048]; axis stride 6144
    const int tid = threadIdx.x;
    const size_t base = (size_t)blockIdx.x * SSP;

    for (int i = tid; i < SSP; i += 512) s[i] = x[base + i];
    __syncthreads();

    for (int t = tid; t < 2048; t += 512) {
        const int l = t >> 1, p = t & 1;
        // D axis: line (h,w) = l, stride 1 (step 2)
        {
            const float* bp = s + l * 32 + p;
            float m1 = 1e30f, m2 = 1e30f; int i1 = -1;
            #pragma unroll
            for (int kk = 0; kk < 16; ++kk) {
                float v = bp[kk * 2];
                if (v < m1) { m2 = m1; m1 = v; i1 = p + 2 * kk; }
                else if (v < m2) { m2 = v; }
            }
            st[t] = m1; st[2048 + t] = m2; st[4096 + t] = (float)i1;
        }
        // W axis: line (h,d): h=l>>5, d=l&31, stride 32 (step 64)
        {
            const float* bp = s + (l >> 5) * 1024 + (l & 31) + p * 32;
            float m1 = 1e30f, m2 = 1e30f; int i1 = -1;
            #pragma unroll
            for (int kk = 0; kk < 16; ++kk) {
                float v = bp[kk * 64];
                if (v < m1) { m2 = m1; m1 = v; i1 = p + 2 * kk; }
                else if (v < m2) { m2 = v; }
            }
            st[6144 + t] = m1; st[6144 + 2048 + t] = m2; st[6144 + 4096 + t] = (float)i1;
        }
        // H axis: line (w,d) = l, stride 1024 (step 2048)
        {
            const float* bp = s + l + p * 1024;
            float m1 = 1e30f, m2 = 1e30f; int i1 = -1;
            #pragma unroll
            for (int kk = 0; kk < 16; ++kk) {
                float v = bp[kk * 2048];
                if (v < m1) { m2 = m1; m1 = v; i1 = p + 2 * kk; }
                else if (v < m2) { m2 = v; }
            }
            st[12288 + t] = m1; st[12288 + 2048 + t] = m2; st[12288 + 4096 + t] = (float)i1;
        }
    }
    __syncthreads();

    for (int i = tid; i < SSP; i += 512) {
        const int d = i & 31, w = (i >> 5) & 31, h = i >> 10;
        const float v = s[i];
        const int tD = (((h << 5) | w) << 1) | (d & 1);
        const float eD = ((float)d == st[4096 + tD]) ? st[2048 + tD] : st[tD];
        const int tW = (((h << 5) | d) << 1) | (w & 1);
        const float eW = ((float)w == st[6144 + 4096 + tW]) ? st[6144 + 2048 + tW] : st[6144 + tW];
        const int tH = (((w << 5) | d) << 1) | (h & 1);
        const float eH = ((float)h == st[12288 + 4096 + tH]) ? st[12288 + 2048 + tH] : st[12288 + tH];
        const float m = fminf(eD, fminf(eW, eH));
        g_xj[base + i] = fmaxf(0.0f, v - m);
    }
}

// ---------------------------------------------------------------------------
// Kernel 2: transpose conv_w [128][256] -> g_wt [256][128]
// ---------------------------------------------------------------------------
__global__ void wt_kernel(const float* __restrict__ w) {
    const int i = blockIdx.x * 256 + threadIdx.x;   // 32768 total
    const int o = i >> 8, k = i & 255;
    g_wt[k * 128 + o] = w[i];
}

// ---------------------------------------------------------------------------
// Kernel 3: GEMM y[b,o,s] = sum_c W[o,c]*act[b,c,s] + bias[o], act = [x; x_j].
// 1024 CTAs: each does all 128 o x 128 spatial, K=256 in chunks of 32.
// 8x8 micro-tile per thread, packed f32x2 FMAs (FFMA2). Fused BN partials.
// ---------------------------------------------------------------------------
__device__ __forceinline__ unsigned long long splat2(float w) {
    unsigned long long r;
    asm("mov.b64 %0, {%1, %1};" : "=l"(r) : "f"(w));
    return r;
}
__device__ __forceinline__ void ffma2(unsigned long long& d, unsigned long long a,
                                      unsigned long long b) {
    asm("fma.rn.f32x2 %0, %1, %2, %0;" : "+l"(d) : "l"(a), "l"(b));
}
__device__ __forceinline__ float2 unpk(unsigned long long v) {
    float2 r;
    asm("mov.b64 {%0, %1}, %2;" : "=f"(r.x), "=f"(r.y) : "l"(v));
    return r;
}

__global__ __launch_bounds__(256, 2) void gemm_kernel(const float* __restrict__ x,
                                                      const float* __restrict__ bias,
                                                      float* __restrict__ y) {
    __shared__ float Ws[32][128];
    __shared__ float As[32][128];
    const int tid = threadIdx.x;
    const int cta = blockIdx.x;
    const int b = cta >> 8;
    const int tile = cta & 255;
    const int tx = tid & 15, ty = tid >> 4;   // tx -> n-block, ty -> o-block

    unsigned long long acc[8][4];
    #pragma unroll
    for (int i = 0; i < 8; ++i)
        #pragma unroll
        for (int j = 0; j < 4; ++j) acc[i][j] = 0ull;

    for (int kc = 0; kc < 8; ++kc) {
        const float* src = (kc < 4)
            ? x    + ((size_t)(b * 128 + kc * 32)) * SSP + tile * 128
            : g_xj + ((size_t)(b * 128 + (kc - 4) * 32)) * SSP + tile * 128;
        #pragma unroll
        for (int j = 0; j < 4; ++j) {
            const int f = tid + j * 256;
            const int k = f >> 5, c4 = (f & 31) << 2;
            *(float4*)&As[k][c4] = *(const float4*)&src[(size_t)k * SSP + c4];
            *(float4*)&Ws[k][c4] = *(const float4*)&g_wt[(kc * 32 + k) * 128 + c4];
        }
        __syncthreads();
        #pragma unroll
        for (int k = 0; k < 32; ++k) {
            const ulonglong2 A0 = *(const ulonglong2*)&As[k][tx * 8];
            const ulonglong2 A1 = *(const ulonglong2*)&As[k][tx * 8 + 4];
            unsigned long long a[4] = {A0.x, A0.y, A1.x, A1.y};
            const float4 w0 = *(const float4*)&Ws[k][ty * 8];
            const float4 w1 = *(const float4*)&Ws[k][ty * 8 + 4];
            unsigned long long wp[8];
            wp[0] = splat2(w0.x); wp[1] = splat2(w0.y);
            wp[2] = splat2(w0.z); wp[3] = splat2(w0.w);
            wp[4] = splat2(w1.x); wp[5] = splat2(w1.y);
            wp[6] = splat2(w1.z); wp[7] = splat2(w1.w);
            #pragma unroll
            for (int i = 0; i < 8; ++i)
                #pragma unroll
                for (int j = 0; j < 4; ++j) ffma2(acc[i][j], wp[i], a[j]);
        }
        __syncthreads();
    }

    // Epilogue: bias, store y, fused BN partial sums (deterministic per-CTA)
    const int an = tile * 128 + tx * 8;
    #pragma unroll
    for (int i = 0; i < 8; ++i) {
        const int o = ty * 8 + i;
        const float bo = __ldg(&bias[o]);
        float r[8];
        #pragma unroll
        for (int j = 0; j < 4; ++j) {
            const float2 u = unpk(acc[i][j]);
            r[2 * j]     = u.x + bo;
            r[2 * j + 1] = u.y + bo;
        }
        float s1 = 0.0f, s2 = 0.0f;
        #pragma unroll
        for (int j = 0; j < 8; ++j) { s1 += r[j]; s2 += r[j] * r[j]; }
        float* dst = y + ((size_t)(b * 128 + o)) * SSP + an;
        *(float4*)dst       = make_float4(r[0], r[1], r[2], r[3]);
        *(float4*)(dst + 4) = make_float4(r[4], r[5], r[6], r[7]);
        #pragma unroll
        for (int ofs = 8; ofs > 0; ofs >>= 1) {
            s1 += __shfl_down_sync(0xffffffffu, s1, ofs, 16);
            s2 += __shfl_down_sync(0xffffffffu, s2, ofs, 16);
        }
        if (tx == 0) {
            g_part[cta * 128 + o]                      = s1;
            g_part[NCTA_GEMM * 128 + cta * 128 + o]    = s2;
        }
    }
}

// ---------------------------------------------------------------------------
// Kernel 4: deterministic fixed-order reduction of partials -> scale/shift
// ---------------------------------------------------------------------------
__global__ void stats_kernel(const float* __restrict__ gamma,
                             const float* __restrict__ beta) {
    const int o = threadIdx.x;
    float s1 = 0.0f, s2 = 0.0f;
    for (int c = 0; c < NCTA_GEMM; ++c) {
        s1 += g_part[c * 128 + o];
        s2 += g_part[NCTA_GEMM * 128 + c * 128 + o];
    }
    const float invN = 1.0f / 131072.0f;   // B*H*W*D
    const float mean = s1 * invN;
    const float var  = fmaxf(s2 * invN - mean * mean, 0.0f);
    const float rstd = rsqrtf(var + 1e-5f);
    const float g = gamma[o];
    g_scale[o] = rstd * g;
    g_shift[o] = beta[o] - mean * rstd * g;
}

// ---------------------------------------------------------------------------
// Kernel 5: in-place BN affine + exact-erf GELU, float4 vectorized
// ---------------------------------------------------------------------------
__global__ __launch_bounds__(256) void bn_gelu_kernel(float* __restrict__ y) {
    const int i4 = blockIdx.x * 256 + threadIdx.x;   // float4 index
    const int o = (i4 >> 13) & 127;                  // (i4*4 / 32768) % 128
    const float sc = g_scale[o], sh = g_shift[o];
    float4 v = ((float4*)y)[i4];
    float t;
    t = fmaf(v.x, sc, sh); v.x = t * normcdff(t);
    t = fmaf(v.y, sc, sh); v.y = t * normcdff(t);
    t = fmaf(v.z, sc, sh); v.z = t * normcdff(t);
    t = fmaf(v.w, sc, sh); v.w = t * normcdff(t);
    ((float4*)y)[i4] = v;
}

// ---------------------------------------------------------------------------
extern "C" void kernel_launch(void* const* d_in, const int* in_sizes, int n_in,
                              void* d_out, int out_size) {
    const float* x      = (const float*)d_in[0];
    const float* conv_w = (const float*)d_in[1];
    const float* conv_b = (const float*)d_in[2];
    const float* gamma  = (const float*)d_in[3];
    const float* beta   = (const float*)d_in[4];
    float* y = (float*)d_out;

    cudaFuncSetAttribute(xj_kernel, cudaFuncAttributeMaxDynamicSharedMemorySize, 204800);

    wt_kernel<<<128, 256>>>(conv_w);
    xj_kernel<<<512, 512, 204800>>>(x);
    gemm_kernel<<<NCTA_GEMM, 256>>>(x, conv_b, y);
    stats_kernel<<<1, 128>>>(gamma, beta);
    bn_gelu_kernel<<<16384, 256>>>(y);
}

// round 7
// speedup vs baseline: 1.5950x; 1.5950x over previous
#include <cuda_runtime.h>
#include <cuda_bf16.h>
#include <cstdint>

// Problem constants
#define SSP 32768           // H*W*D
#define NB 4
#define NPART 4096          // gemm partials: 1024 CTAs * 4 n-warp-groups

// Scratch (no allocations allowed)
__device__ float g_xj[NB * 128 * SSP];                      // 64MB
__device__ __align__(16) __nv_bfloat16 g_wbh[128 * 256];    // W hi, row-major [o][k]
__device__ __align__(16) __nv_bfloat16 g_wbl[128 * 256];    // W lo, row-major [o][k]
__device__ float g_part[2 * NPART * 128];
__device__ float g_part2[2 * 64 * 128];
__device__ float g_scale[128];
__device__ float g_shift[128];

// Single dynamic-SMEM symbol shared by all kernels (extern shared arrays must
// have one consistent type per TU).
extern __shared__ char dyn_smem[];

// ---------------------------------------------------------------------------
// mma.sync / ldmatrix helpers (sm_80+ PTX; valid under plain sm_100 target)
// ---------------------------------------------------------------------------
__device__ __forceinline__ uint32_t smem_u32(const void* p) {
    uint32_t a;
    asm("{ .reg .u64 t; cvta.to.shared.u64 t, %1; cvt.u32.u64 %0, t; }" : "=r"(a) : "l"(p));
    return a;
}
__device__ __forceinline__ void ldsm4(uint32_t addr, uint32_t* r) {
    asm volatile("ldmatrix.sync.aligned.m8n8.x4.shared.b16 {%0,%1,%2,%3}, [%4];"
                 : "=r"(r[0]), "=r"(r[1]), "=r"(r[2]), "=r"(r[3]) : "r"(addr));
}
__device__ __forceinline__ void ldsm4t(uint32_t addr, uint32_t* r) {
    asm volatile("ldmatrix.sync.aligned.m8n8.x4.trans.shared.b16 {%0,%1,%2,%3}, [%4];"
                 : "=r"(r[0]), "=r"(r[1]), "=r"(r[2]), "=r"(r[3]) : "r"(addr));
}
__device__ __forceinline__ void mma_bf16(float* d, const uint32_t* a, uint32_t b0, uint32_t b1) {
    asm volatile("mma.sync.aligned.m16n8k16.row.col.f32.bf16.bf16.f32 "
                 "{%0,%1,%2,%3}, {%4,%5,%6,%7}, {%8,%9}, {%0,%1,%2,%3};"
                 : "+f"(d[0]), "+f"(d[1]), "+f"(d[2]), "+f"(d[3])
                 : "r"(a[0]), "r"(a[1]), "r"(a[2]), "r"(a[3]), "r"(b0), "r"(b1));
}
__device__ __forceinline__ uint32_t pk2(__nv_bfloat16 a, __nv_bfloat16 b) {
    __nv_bfloat162 t; t.x = a; t.y = b; return *(uint32_t*)&t;
}

// ---------------------------------------------------------------------------
// Kernel 1: x_j. One CTA per (b,c) slice held in SMEM.
// x_j = max(0, x - min over same-parity-excluding-self along each axis).
// ---------------------------------------------------------------------------
__global__ __launch_bounds__(1024) void xj_kernel(const float* __restrict__ x) {
    float* s  = (float*)dyn_smem;
    float* st = (float*)dyn_smem + 32768;
    const int tid = threadIdx.x;
    const size_t base = (size_t)blockIdx.x * SSP;

    for (int i = tid; i < SSP; i += 1024) s[i] = x[base + i];
    __syncthreads();

    for (int t = tid; t < 2048; t += 1024) {
        const int l = t >> 1, p = t & 1;
        {   // D axis
            const float* bp = s + l * 32 + p;
            float m1 = 1e30f, m2 = 1e30f; int i1 = -1;
            #pragma unroll
            for (int kk = 0; kk < 16; ++kk) {
                float v = bp[kk * 2];
                if (v < m1) { m2 = m1; m1 = v; i1 = p + 2 * kk; } else if (v < m2) m2 = v;
            }
            st[t] = m1; st[2048 + t] = m2; st[4096 + t] = (float)i1;
        }
        {   // W axis
            const float* bp = s + (l >> 5) * 1024 + (l & 31) + p * 32;
            float m1 = 1e30f, m2 = 1e30f; int i1 = -1;
            #pragma unroll
            for (int kk = 0; kk < 16; ++kk) {
                float v = bp[kk * 64];
                if (v < m1) { m2 = m1; m1 = v; i1 = p + 2 * kk; } else if (v < m2) m2 = v;
            }
            st[6144 + t] = m1; st[6144 + 2048 + t] = m2; st[6144 + 4096 + t] = (float)i1;
        }
        {   // H axis
            const float* bp = s + l + p * 1024;
            float m1 = 1e30f, m2 = 1e30f; int i1 = -1;
            #pragma unroll
            for (int kk = 0; kk < 16; ++kk) {
                float v = bp[kk * 2048];
                if (v < m1) { m2 = m1; m1 = v; i1 = p + 2 * kk; } else if (v < m2) m2 = v;
            }
            st[12288 + t] = m1; st[12288 + 2048 + t] = m2; st[12288 + 4096 + t] = (float)i1;
        }
    }
    __syncthreads();

    for (int i = tid; i < SSP; i += 1024) {
        const int d = i & 31, w = (i >> 5) & 31, h = i >> 10;
        const float v = s[i];
        const int tD = (((h << 5) | w) << 1) | (d & 1);
        const float eD = ((float)d == st[4096 + tD]) ? st[2048 + tD] : st[tD];
        const int tW = (((h << 5) | d) << 1) | (w & 1);
        const float eW = ((float)w == st[6144 + 4096 + tW]) ? st[6144 + 2048 + tW] : st[6144 + tW];
        const int tH = (((w << 5) | d) << 1) | (h & 1);
        const float eH = ((float)h == st[12288 + 4096 + tH]) ? st[12288 + 2048 + tH] : st[12288 + tH];
        g_xj[base + i] = fmaxf(0.0f, v - fminf(eD, fminf(eW, eH)));
    }
}

// ---------------------------------------------------------------------------
// Kernel 2: W -> bf16 hi/lo, plain row-major [o][k]
// ---------------------------------------------------------------------------
__global__ void wb_kernel(const float* __restrict__ w) {
    const int i = blockIdx.x * 256 + threadIdx.x;   // 32768 = 128*256
    const float v = w[i];
    const __nv_bfloat16 h = __float2bfloat16(v);
    const __nv_bfloat16 l = __float2bfloat16(v - __bfloat162float(h));
    g_wbh[i] = h;
    g_wbl[i] = l;
}

// ---------------------------------------------------------------------------
// Kernel 3: bf16 split-precision GEMM via mma.sync (HMMA) + bias + BN partials.
// D[o(128), s(128)] = sum_k W[o,k] * act[k,s], act=[x;x_j], K=256, per (b,tile).
// A = W full-K in SMEM (hi+lo). B = act, K-chunks of 64, double-buffered,
// reg-staged global loads overlapped with MMA. 3 products: AhBh + AhBl + AlBh.
// Warp grid 2(m) x 4(n): each warp 64(o) x 32(s).
// ---------------------------------------------------------------------------
#define ASTR 264                      // bf16 elems per A row (33x16B, conflict-free)
#define BSTR 136                      // bf16 elems per B row (17x16B, conflict-free)
#define A_BYTES (128 * ASTR * 2)      // 67584
#define BCH_BYTES (64 * BSTR * 2)     // 17408
#define OFF_B (2 * A_BYTES)
#define GEMM_SMEM (2 * A_BYTES + 4 * BCH_BYTES)   // 204800

__global__ __launch_bounds__(256, 1) void gemm_kernel(const float* __restrict__ x,
                                                      const float* __restrict__ bias,
                                                      float* __restrict__ y) {
    char* sm = dyn_smem;
    __shared__ float sbias[128];
    const int tid = threadIdx.x, l = tid & 31, wid = tid >> 5;
    const int cta = blockIdx.x, b = cta >> 8, tile = cta & 255;
    const int wm = (wid & 1) * 64;        // o-offset of this warp
    const int wn = (wid >> 1) * 32;       // s-offset of this warp
    const uint32_t smb = smem_u32(sm);

    if (tid < 128) sbias[tid] = bias[tid];

    // Prologue: W (hi+lo) into SMEM. 4096 float4 per matrix.
    {
        const float4* sh = (const float4*)g_wbh;
        const float4* sl = (const float4*)g_wbl;
        #pragma unroll
        for (int j = 0; j < 16; ++j) {
            const int idx = tid + j * 256;          // 0..4095
            const int o = idx >> 5, c4 = idx & 31;  // k = c4*8
            *(float4*)(sm + o * (ASTR * 2) + c4 * 16) = sh[idx];
            *(float4*)(sm + A_BYTES + o * (ASTR * 2) + c4 * 16) = sl[idx];
        }
    }

    float4 rv[8];
    // load act chunk ch (64 k-rows x 128 s) into registers
    auto LDACT = [&](int ch) {
        const float* src = (ch < 2 ? x : g_xj)
                           + ((size_t)(b * 128 + (ch & 1) * 64)) * SSP + tile * 128;
        #pragma unroll
        for (int j = 0; j < 8; ++j) {
            const int idx = tid + j * 256;          // 0..2047
            const int k = idx >> 5, c4 = idx & 31;
            rv[j] = *(const float4*)&src[(size_t)k * SSP + c4 * 4];
        }
    };
    // convert rv to bf16 hi/lo and store into buffer `buf`
    auto STACT = [&](int buf) {
        char* base = sm + OFF_B + buf * 2 * BCH_BYTES;
        #pragma unroll
        for (int j = 0; j < 8; ++j) {
            const int idx = tid + j * 256;
            const int k = idx >> 5, c4 = idx & 31;
            const float4 v = rv[j];
            const __nv_bfloat16 h0 = __float2bfloat16(v.x);
            const __nv_bfloat16 h1 = __float2bfloat16(v.y);
            const __nv_bfloat16 h2 = __float2bfloat16(v.z);
            const __nv_bfloat16 h3 = __float2bfloat16(v.w);
            const __nv_bfloat16 l0 = __float2bfloat16(v.x - __bfloat162float(h0));
            const __nv_bfloat16 l1 = __float2bfloat16(v.y - __bfloat162float(h1));
            const __nv_bfloat16 l2 = __float2bfloat16(v.z - __bfloat162float(h2));
            const __nv_bfloat16 l3 = __float2bfloat16(v.w - __bfloat162float(h3));
            *(uint2*)(base + k * (BSTR * 2) + c4 * 8) = make_uint2(pk2(h0, h1), pk2(h2, h3));
            *(uint2*)(base + BCH_BYTES + k * (BSTR * 2) + c4 * 8) = make_uint2(pk2(l0, l1), pk2(l2, l3));
        }
    };

    LDACT(0); STACT(0);
    __syncthreads();

    float acc[16][4];
    #pragma unroll
    for (int i = 0; i < 16; ++i)
        #pragma unroll
        for (int j = 0; j < 4; ++j) acc[i][j] = 0.0f;

    #pragma unroll 1
    for (int ch = 0; ch < 4; ++ch) {
        if (ch < 3) LDACT(ch + 1);
        const uint32_t Bh = smb + OFF_B + (ch & 1) * 2 * BCH_BYTES;
        #pragma unroll
        for (int ks = 0; ks < 4; ++ks) {
            const int kg = ch * 64 + ks * 16;   // absolute k (A holds full K)
            const int kl = ks * 16;             // local k within B chunk
            uint32_t ah[4][4], al[4][4];
            #pragma unroll
            for (int mi = 0; mi < 4; ++mi) {
                const uint32_t ra = smb + (wm + mi * 16 + (l & 15)) * (ASTR * 2)
                                    + (kg + (l >> 4) * 8) * 2;
                ldsm4(ra, ah[mi]);
                ldsm4(ra + A_BYTES, al[mi]);
            }
            uint32_t bh[2][4], bl[2][4];
            #pragma unroll
            for (int ng = 0; ng < 2; ++ng) {
                const uint32_t rb = Bh + (kl + (l & 15)) * (BSTR * 2)
                                    + (wn + ng * 16 + (l >> 4) * 8) * 2;
                ldsm4t(rb, bh[ng]);
                ldsm4t(rb + BCH_BYTES, bl[ng]);
            }
            #pragma unroll
            for (int mi = 0; mi < 4; ++mi)
                #pragma unroll
                for (int ni = 0; ni < 4; ++ni) {
                    float* d = acc[mi * 4 + ni];
                    const uint32_t* hb = &bh[ni >> 1][(ni & 1) * 2];
                    const uint32_t* lb = &bl[ni >> 1][(ni & 1) * 2];
                    mma_bf16(d, ah[mi], hb[0], hb[1]);   // hi*hi
                    mma_bf16(d, ah[mi], lb[0], lb[1]);   // hi*lo
                    mma_bf16(d, al[mi], hb[0], hb[1]);   // lo*hi
                }
        }
        __syncthreads();
        if (ch < 3) { STACT((ch + 1) & 1); __syncthreads(); }
    }

    // Epilogue: bias, store y, fused deterministic BN partials.
    const int row = l >> 2, colp = (l & 3) * 2;
    #pragma unroll
    for (int mi = 0; mi < 4; ++mi) {
        #pragma unroll
        for (int rr = 0; rr < 2; ++rr) {
            const int o = wm + mi * 16 + row + rr * 8;
            const float bo = sbias[o];
            float s1 = 0.0f, s2 = 0.0f;
            float* obase = y + ((size_t)(b * 128 + o)) * SSP + tile * 128 + wn + colp;
            #pragma unroll
            for (int ni = 0; ni < 4; ++ni) {
                const float v0 = acc[mi * 4 + ni][rr * 2 + 0] + bo;
                const float v1 = acc[mi * 4 + ni][rr * 2 + 1] + bo;
                *(float2*)(obase + ni * 8) = make_float2(v0, v1);
                s1 += v0 + v1;
                s2 += v0 * v0 + v1 * v1;
            }
            s1 += __shfl_xor_sync(0xffffffffu, s1, 1);
            s2 += __shfl_xor_sync(0xffffffffu, s2, 1);
            s1 += __shfl_xor_sync(0xffffffffu, s1, 2);
            s2 += __shfl_xor_sync(0xffffffffu, s2, 2);
            if ((l & 3) == 0) {
                const int pidx = (cta * 4 + (wid >> 1)) * 128 + o;
                g_part[pidx] = s1;
                g_part[NPART * 128 + pidx] = s2;
            }
        }
    }
}

// ---------------------------------------------------------------------------
// Kernel 4a/4b: parallel deterministic reduction of partials -> scale/shift
// ---------------------------------------------------------------------------
__global__ void stats1_kernel() {
    __shared__ float r1[256], r2[256];
    const int bb = blockIdx.x;           // 0..63
    const int tid = threadIdx.x;         // 256
    const int o = tid & 127, half = tid >> 7;
    float s1 = 0.0f, s2 = 0.0f;
    for (int c = half; c < 64; c += 2) {
        const int idx = (bb * 64 + c) * 128 + o;
        s1 += g_part[idx];
        s2 += g_part[NPART * 128 + idx];
    }
    r1[tid] = s1; r2[tid] = s2;
    __syncthreads();
    if (half == 0) {
        g_part2[bb * 128 + o] = r1[tid] + r1[tid + 128];
        g_part2[64 * 128 + bb * 128 + o] = r2[tid] + r2[tid + 128];
    }
}

__global__ void stats2_kernel(const float* __restrict__ gamma,
                              const float* __restrict__ beta) {
    const int o = threadIdx.x;
    float s1 = 0.0f, s2 = 0.0f;
    for (int c = 0; c < 64; ++c) {
        s1 += g_part2[c * 128 + o];
        s2 += g_part2[64 * 128 + c * 128 + o];
    }
    const float invN = 1.0f / 131072.0f;
    const float mean = s1 * invN;
    const float var = fmaxf(s2 * invN - mean * mean, 0.0f);
    const float rstd = rsqrtf(var + 1e-5f);
    const float g = gamma[o];
    g_scale[o] = rstd * g;
    g_shift[o] = beta[o] - mean * rstd * g;
}

// ---------------------------------------------------------------------------
// Kernel 5: in-place BN affine + exact-erf GELU
// ---------------------------------------------------------------------------
__global__ __launch_bounds__(256) void bn_gelu_kernel(float* __restrict__ y) {
    const int i4 = blockIdx.x * 256 + threadIdx.x;
    const int o = (i4 >> 13) & 127;
    const float sc = g_scale[o], sh = g_shift[o];
    float4 v = ((float4*)y)[i4];
    float t;
    t = fmaf(v.x, sc, sh); v.x = t * normcdff(t);
    t = fmaf(v.y, sc, sh); v.y = t * normcdff(t);
    t = fmaf(v.z, sc, sh); v.z = t * normcdff(t);
    t = fmaf(v.w, sc, sh); v.w = t * normcdff(t);
    ((float4*)y)[i4] = v;
}

// ---------------------------------------------------------------------------
extern "C" void kernel_launch(void* const* d_in, const int* in_sizes, int n_in,
                              void* d_out, int out_size) {
    const float* x      = (const float*)d_in[0];
    const float* conv_w = (const float*)d_in[1];
    const float* conv_b = (const float*)d_in[2];
    const float* gamma  = (const float*)d_in[3];
    const float* beta   = (const float*)d_in[4];
    float* y = (float*)d_out;

    cudaFuncSetAttribute(xj_kernel, cudaFuncAttributeMaxDynamicSharedMemorySize, 204800);
    cudaFuncSetAttribute(gemm_kernel, cudaFuncAttributeMaxDynamicSharedMemorySize, GEMM_SMEM);

    wb_kernel<<<128, 256>>>(conv_w);
    xj_kernel<<<512, 1024, 204800>>>(x);
    gemm_kernel<<<1024, 256, GEMM_SMEM>>>(x, conv_b, y);
    stats1_kernel<<<64, 256>>>();
    stats2_kernel<<<1, 128>>>(gamma, beta);
    bn_gelu_kernel<<<16384, 256>>>(y);
}